// round 1
// baseline (speedup 1.0000x reference)
#include <cuda_runtime.h>
#include <cuda_bf16.h>

// Weighted keypoint MSE loss:
//   oob = target outside [0,1024]x[0,1024]; weight = oob ? 0.01 : 1.0
//   loss = sum_bk( weight * ||output-target||^2 ) / B
//
// HBM-bound streaming reduction: float4 loads (2 keypoints per vec),
// double per-thread accumulation, block reduce, atomicAdd(double).

#define HEIGHT_F 1024.0f
#define WIDTH_F  1024.0f
#define OOB_W    0.01f
#define B_DIM    4096.0

__device__ double g_loss_sum;

__global__ void zero_accum_kernel() {
    g_loss_sum = 0.0;
}

__global__ __launch_bounds__(256) void loss_kernel(
    const float4* __restrict__ outp,
    const float4* __restrict__ tgt,
    long long n4)
{
    double acc = 0.0;
    long long idx = (long long)blockIdx.x * blockDim.x + threadIdx.x;
    long long stride = (long long)gridDim.x * blockDim.x;

    for (long long i = idx; i < n4; i += stride) {
        float4 o = outp[i];
        float4 t = tgt[i];

        // keypoint 0: (o.x,o.y) vs (t.x,t.y)
        float dx0 = o.x - t.x;
        float dy0 = o.y - t.y;
        float sq0 = fmaf(dx0, dx0, dy0 * dy0);
        bool oob0 = (t.x < 0.0f) || (t.x > WIDTH_F) || (t.y < 0.0f) || (t.y > HEIGHT_F);
        float w0 = oob0 ? OOB_W : 1.0f;

        // keypoint 1: (o.z,o.w) vs (t.z,t.w)
        float dx1 = o.z - t.z;
        float dy1 = o.w - t.w;
        float sq1 = fmaf(dx1, dx1, dy1 * dy1);
        bool oob1 = (t.z < 0.0f) || (t.z > WIDTH_F) || (t.w < 0.0f) || (t.w > HEIGHT_F);
        float w1 = oob1 ? OOB_W : 1.0f;

        acc += (double)fmaf(w0, sq0, w1 * sq1);
    }

    // warp reduce
    #pragma unroll
    for (int off = 16; off > 0; off >>= 1)
        acc += __shfl_down_sync(0xFFFFFFFFu, acc, off);

    __shared__ double warp_sums[8];
    int lane = threadIdx.x & 31;
    int wid  = threadIdx.x >> 5;
    if (lane == 0) warp_sums[wid] = acc;
    __syncthreads();

    if (wid == 0) {
        double v = (lane < (blockDim.x >> 5)) ? warp_sums[lane] : 0.0;
        #pragma unroll
        for (int off = 4; off > 0; off >>= 1)
            v += __shfl_down_sync(0xFFFFFFFFu, v, off);
        if (lane == 0)
            atomicAdd(&g_loss_sum, v);
    }
}

__global__ void finalize_kernel(float* __restrict__ out) {
    out[0] = (float)(g_loss_sum / B_DIM);
}

extern "C" void kernel_launch(void* const* d_in, const int* in_sizes, int n_in,
                              void* d_out, int out_size) {
    const float4* outp = (const float4*)d_in[0];
    const float4* tgt  = (const float4*)d_in[1];
    long long n_elems = (long long)in_sizes[0];   // 4096*4096*2 floats
    long long n4 = n_elems / 4;                   // float4 count (2 keypoints each)

    zero_accum_kernel<<<1, 1>>>();

    int threads = 256;
    int blocks = 148 * 8;  // 1184 blocks: full-chip, plenty of MLP per SM
    loss_kernel<<<blocks, threads>>>(outp, tgt, n4);

    finalize_kernel<<<1, 1>>>((float*)d_out);
}

// round 2
// speedup vs baseline: 1.0157x; 1.0157x over previous
#include <cuda_runtime.h>
#include <cuda_bf16.h>

// Weighted keypoint MSE loss, single fused kernel:
//   oob = target outside [0,1024]^2; weight = oob ? 0.01 : 1.0
//   loss = sum_bk( weight * ||output-target||^2 ) / 4096
//
// HBM-bound streaming reduction. float4 loads (2 keypoints/vec), 4x unrolled
// grid-stride for MLP=8, float inner sums -> double per-thread accumulator,
// block reduce -> partials array -> last-block finalize (threadfence pattern,
// atomicInc self-wraps so no reset kernel is needed; graph-replay safe).

#define HEIGHT_F 1024.0f
#define WIDTH_F  1024.0f
#define OOB_W    0.01f
#define B_DIM    4096.0

#define NBLOCKS  1024
#define NTHREADS 256

__device__ double g_partials[NBLOCKS];
__device__ unsigned int g_count;   // zero-init at module load; self-wraps each run

__device__ __forceinline__ float pair_loss(float4 o, float4 t) {
    float dx0 = o.x - t.x;
    float dy0 = o.y - t.y;
    float sq0 = fmaf(dx0, dx0, dy0 * dy0);
    bool oob0 = (t.x < 0.0f) | (t.x > WIDTH_F) | (t.y < 0.0f) | (t.y > HEIGHT_F);
    float w0 = oob0 ? OOB_W : 1.0f;

    float dx1 = o.z - t.z;
    float dy1 = o.w - t.w;
    float sq1 = fmaf(dx1, dx1, dy1 * dy1);
    bool oob1 = (t.z < 0.0f) | (t.z > WIDTH_F) | (t.w < 0.0f) | (t.w > HEIGHT_F);
    float w1 = oob1 ? OOB_W : 1.0f;

    return fmaf(w0, sq0, w1 * sq1);
}

__device__ __forceinline__ double block_reduce(double v, double* warp_sums) {
    #pragma unroll
    for (int off = 16; off > 0; off >>= 1)
        v += __shfl_down_sync(0xFFFFFFFFu, v, off);
    int lane = threadIdx.x & 31;
    int wid  = threadIdx.x >> 5;
    if (lane == 0) warp_sums[wid] = v;
    __syncthreads();
    if (wid == 0) {
        v = (lane < (NTHREADS >> 5)) ? warp_sums[lane] : 0.0;
        #pragma unroll
        for (int off = 4; off > 0; off >>= 1)
            v += __shfl_down_sync(0xFFFFFFFFu, v, off);
    }
    return v;  // valid in thread 0
}

__global__ __launch_bounds__(NTHREADS) void loss_kernel(
    const float4* __restrict__ outp,
    const float4* __restrict__ tgt,
    long long n4,
    float* __restrict__ out)
{
    double acc = 0.0;
    long long stride = (long long)gridDim.x * blockDim.x;
    long long i = (long long)blockIdx.x * blockDim.x + threadIdx.x;

    // main loop: 4x unrolled, 8 independent 16B loads in flight per thread
    for (; i + 3 * stride < n4; i += 4 * stride) {
        float4 o0 = __ldcs(outp + i);
        float4 o1 = __ldcs(outp + i + stride);
        float4 o2 = __ldcs(outp + i + 2 * stride);
        float4 o3 = __ldcs(outp + i + 3 * stride);
        float4 t0 = __ldcs(tgt + i);
        float4 t1 = __ldcs(tgt + i + stride);
        float4 t2 = __ldcs(tgt + i + 2 * stride);
        float4 t3 = __ldcs(tgt + i + 3 * stride);

        float s = pair_loss(o0, t0);
        s += pair_loss(o1, t1);
        s += pair_loss(o2, t2);
        s += pair_loss(o3, t3);
        acc += (double)s;
    }
    // tail (not taken for 4096x4096x2 shape, kept for generality)
    for (; i < n4; i += stride) {
        float4 o = __ldcs(outp + i);
        float4 t = __ldcs(tgt + i);
        acc += (double)pair_loss(o, t);
    }

    __shared__ double warp_sums[NTHREADS / 32];
    __shared__ bool is_last;

    double bsum = block_reduce(acc, warp_sums);

    if (threadIdx.x == 0) {
        g_partials[blockIdx.x] = bsum;
        __threadfence();
        // atomicInc wraps to 0 when old == gridDim.x-1 -> deterministic reset
        unsigned int old = atomicInc(&g_count, gridDim.x - 1);
        is_last = (old == gridDim.x - 1);
    }
    __syncthreads();

    if (is_last) {
        __threadfence();  // acquire all blocks' partials
        double v = 0.0;
        for (int j = threadIdx.x; j < (int)gridDim.x; j += blockDim.x)
            v += g_partials[j];
        __syncthreads();  // reuse warp_sums safely
        double total = block_reduce(v, warp_sums);
        if (threadIdx.x == 0)
            out[0] = (float)(total / B_DIM);
    }
}

extern "C" void kernel_launch(void* const* d_in, const int* in_sizes, int n_in,
                              void* d_out, int out_size) {
    const float4* outp = (const float4*)d_in[0];
    const float4* tgt  = (const float4*)d_in[1];
    long long n_elems = (long long)in_sizes[0];   // 4096*4096*2 floats
    long long n4 = n_elems / 4;                   // float4 count

    loss_kernel<<<NBLOCKS, NTHREADS>>>(outp, tgt, n4, (float*)d_out);
}

// round 3
// speedup vs baseline: 1.1444x; 1.1267x over previous
#include <cuda_runtime.h>
#include <cuda_bf16.h>

// Weighted keypoint MSE loss, single fused kernel:
//   oob = target outside [0,1024]^2; weight = oob ? 0.01 : 1.0
//   loss = sum_bk( weight * ||output-target||^2 ) / 4096
//
// HBM-bound streaming reduction.
// R3 tuning: grid = 148*8 (exact wave balance), 32-bit indices, unroll-2
// (MLP=4/thread, full 64-warp occupancy), last-block finalize.

#define HEIGHT_F 1024.0f
#define WIDTH_F  1024.0f
#define OOB_W    0.01f
#define B_DIM    4096.0

#define NBLOCKS  1184   // 148 SMs * 8 CTAs
#define NTHREADS 256

__device__ double g_partials[NBLOCKS];
__device__ unsigned int g_count;   // zero-init; atomicInc self-wraps -> replay-safe

__device__ __forceinline__ float pair_loss(float4 o, float4 t) {
    float dx0 = o.x - t.x;
    float dy0 = o.y - t.y;
    float sq0 = fmaf(dx0, dx0, dy0 * dy0);
    bool oob0 = (t.x < 0.0f) | (t.x > WIDTH_F) | (t.y < 0.0f) | (t.y > HEIGHT_F);
    float w0 = oob0 ? OOB_W : 1.0f;

    float dx1 = o.z - t.z;
    float dy1 = o.w - t.w;
    float sq1 = fmaf(dx1, dx1, dy1 * dy1);
    bool oob1 = (t.z < 0.0f) | (t.z > WIDTH_F) | (t.w < 0.0f) | (t.w > HEIGHT_F);
    float w1 = oob1 ? OOB_W : 1.0f;

    return fmaf(w0, sq0, w1 * sq1);
}

__device__ __forceinline__ double block_reduce(double v, double* warp_sums) {
    #pragma unroll
    for (int off = 16; off > 0; off >>= 1)
        v += __shfl_down_sync(0xFFFFFFFFu, v, off);
    int lane = threadIdx.x & 31;
    int wid  = threadIdx.x >> 5;
    if (lane == 0) warp_sums[wid] = v;
    __syncthreads();
    if (wid == 0) {
        v = (lane < (NTHREADS >> 5)) ? warp_sums[lane] : 0.0;
        #pragma unroll
        for (int off = 4; off > 0; off >>= 1)
            v += __shfl_down_sync(0xFFFFFFFFu, v, off);
    }
    return v;  // valid in thread 0
}

__global__ __launch_bounds__(NTHREADS, 8) void loss_kernel(
    const float4* __restrict__ outp,
    const float4* __restrict__ tgt,
    int n4,
    float* __restrict__ out)
{
    const int stride = NBLOCKS * NTHREADS;          // 303104, fits int
    int i = blockIdx.x * NTHREADS + threadIdx.x;

    double acc = 0.0;

    // unroll-2: 4 independent LDG.128 in flight per thread
    for (; i + stride < n4; i += 2 * stride) {
        float4 o0 = __ldcs(outp + i);
        float4 t0 = __ldcs(tgt + i);
        float4 o1 = __ldcs(outp + i + stride);
        float4 t1 = __ldcs(tgt + i + stride);
        acc += (double)(pair_loss(o0, t0) + pair_loss(o1, t1));
    }
    for (; i < n4; i += stride) {
        float4 o = __ldcs(outp + i);
        float4 t = __ldcs(tgt + i);
        acc += (double)pair_loss(o, t);
    }

    __shared__ double warp_sums[NTHREADS / 32];
    __shared__ bool is_last;

    double bsum = block_reduce(acc, warp_sums);

    if (threadIdx.x == 0) {
        g_partials[blockIdx.x] = bsum;
        __threadfence();
        unsigned int old = atomicInc(&g_count, NBLOCKS - 1);  // wraps to 0
        is_last = (old == NBLOCKS - 1);
    }
    __syncthreads();

    if (is_last) {
        __threadfence();
        double v = 0.0;
        for (int j = threadIdx.x; j < NBLOCKS; j += NTHREADS)
            v += g_partials[j];
        __syncthreads();
        double total = block_reduce(v, warp_sums);
        if (threadIdx.x == 0)
            out[0] = (float)(total / B_DIM);
    }
}

extern "C" void kernel_launch(void* const* d_in, const int* in_sizes, int n_in,
                              void* d_out, int out_size) {
    const float4* outp = (const float4*)d_in[0];
    const float4* tgt  = (const float4*)d_in[1];
    int n4 = in_sizes[0] / 4;   // float4 count (2 keypoints each)

    loss_kernel<<<NBLOCKS, NTHREADS>>>(outp, tgt, n4, (float*)d_out);
}